// round 14
// baseline (speedup 1.0000x reference)
#include <cuda_runtime.h>
#include <cuda_bf16.h>
#include <math.h>
#include <stdint.h>

#define BB 4
#define TT 2048
#define DD 1024
#define HH 16
#define HD 64
#define MTOT (BB*TT)   // 8192

// ---------------- scratch (device globals: allocation-free) ----------------
__device__ float g_v [MTOT*DD];

__device__ __nv_bfloat16 g_xh [MTOT*DD];
__device__ __nv_bfloat16 g_xl [MTOT*DD];
__device__ __nv_bfloat16 g_aoh[MTOT*DD];
__device__ __nv_bfloat16 g_aol[MTOT*DD];
__device__ __nv_bfloat16 g_wh [4*DD*DD];
__device__ __nv_bfloat16 g_wl [4*DD*DD];

// attention operands (bf16 hi/lo)
__device__ __nv_bfloat16 g_qh [MTOT*DD];
__device__ __nv_bfloat16 g_ql [MTOT*DD];
__device__ __nv_bfloat16 g_kh [MTOT*DD];
__device__ __nv_bfloat16 g_kl [MTOT*DD];
__device__ __nv_bfloat16 g_vth[MTOT*DD];   // [b][h][d][T]
__device__ __nv_bfloat16 g_vtl[MTOT*DD];

// rope table: per (token, freq) cos/sin
__device__ float2 g_rope[MTOT * 32];

// =============================== PTX helpers ===============================
__device__ __forceinline__ uint32_t smem_u32(const void* p) {
    uint32_t a;
    asm("{ .reg .u64 t; cvta.to.shared.u64 t, %1; cvt.u32.u64 %0, t; }" : "=r"(a) : "l"(p));
    return a;
}

#define LDSM4(r, a) \
    asm volatile("ldmatrix.sync.aligned.m8n8.x4.shared.b16 {%0,%1,%2,%3}, [%4];" \
        : "=r"((r)[0]), "=r"((r)[1]), "=r"((r)[2]), "=r"((r)[3]) : "r"(a))

#define MMA16816(d, a, b0, b1) \
    asm volatile("mma.sync.aligned.m16n8k16.row.col.f32.bf16.bf16.f32 " \
        "{%0,%1,%2,%3}, {%4,%5,%6,%7}, {%8,%9}, {%0,%1,%2,%3};" \
        : "+f"((d)[0]), "+f"((d)[1]), "+f"((d)[2]), "+f"((d)[3]) \
        : "r"((a)[0]), "r"((a)[1]), "r"((a)[2]), "r"((a)[3]), "r"(b0), "r"(b1))

#define CP_ASYNC16(dst, src) \
    asm volatile("cp.async.cg.shared.global [%0], [%1], 16;" :: "r"(dst), "l"(src))
#define CP_COMMIT() asm volatile("cp.async.commit_group;" ::: "memory")
#define CP_WAIT0()  asm volatile("cp.async.wait_group 0;" ::: "memory")

// exp2 via magic round + deg-5 poly; input already in log2 domain.
__device__ __forceinline__ float fexp2(float x) {
    x = fmaxf(x, -110.f);
    float zi = x + 12582912.f;
    float fi = zi - 12582912.f;
    float f  = x - fi;
    int   ei = __float_as_int(zi);
    float p = 0.00133335581f;
    p = fmaf(p, f, 0.00961812911f);
    p = fmaf(p, f, 0.05550410866f);
    p = fmaf(p, f, 0.24022650700f);
    p = fmaf(p, f, 0.69314718056f);
    p = fmaf(p, f, 1.0f);
    return __int_as_float(__float_as_int(p) + (ei << 23));
}

__device__ __forceinline__ uint32_t pack_bf2(float a, float b) {
    __nv_bfloat162 h = __float22bfloat162_rn(make_float2(a, b));
    return *(uint32_t*)&h;
}

// split 8 floats -> hi/lo uint4
__device__ __forceinline__ void split8(const float4 a, const float4 b,
                                       uint4* H, uint4* L) {
    uint32_t h0 = pack_bf2(a.x, a.y), h1 = pack_bf2(a.z, a.w);
    uint32_t h2 = pack_bf2(b.x, b.y), h3 = pack_bf2(b.z, b.w);
    float2 r0 = __bfloat1622float2(*(__nv_bfloat162*)&h0);
    float2 r1 = __bfloat1622float2(*(__nv_bfloat162*)&h1);
    float2 r2 = __bfloat1622float2(*(__nv_bfloat162*)&h2);
    float2 r3 = __bfloat1622float2(*(__nv_bfloat162*)&h3);
    *H = make_uint4(h0, h1, h2, h3);
    *L = make_uint4(pack_bf2(a.x - r0.x, a.y - r0.y),
                    pack_bf2(a.z - r1.x, a.w - r1.y),
                    pack_bf2(b.x - r2.x, b.y - r2.y),
                    pack_bf2(b.z - r3.x, b.w - r3.y));
}

// ===========================================================================
// split_all: x + 4 weights -> hi/lo bf16, PLUS rope-table build (tail blocks).
// grid 7168 x 256.
// ===========================================================================
#define XU (MTOT * DD / 8)   // 1048576
#define WU (DD * DD / 8)     // 131072
#define SPLIT_UNITS (XU + 4 * WU)            // 1572864 -> 6144 blocks
#define TBL_BLOCKS (MTOT * 32 / 256)         // 1024 blocks
#define LN_THETA 9.210340371976184f

__global__ __launch_bounds__(256) void split_all(const float* __restrict__ x,
                                                 const float* __restrict__ wq,
                                                 const float* __restrict__ wk,
                                                 const float* __restrict__ wv,
                                                 const float* __restrict__ wo,
                                                 const int* __restrict__ pos) {
    size_t u = (size_t)blockIdx.x * 256 + threadIdx.x;
    if (u >= SPLIT_UNITS) {
        // rope table: t in [0, MTOT*32)
        size_t t = u - SPLIT_UNITS;
        int row = (int)(t >> 5);
        int fi  = (int)(t & 31);
        float p   = (float)pos[row];
        float inv = __expf(-((float)(2 * fi) / 64.0f) * LN_THETA);
        float s, c;
        sincosf(p * inv, &s, &c);
        g_rope[t] = make_float2(c, s);
        return;
    }
    const float* src;
    __nv_bfloat16 *H, *L;
    size_t off;
    if (u < XU) {
        src = x; H = g_xh; L = g_xl; off = u;
    } else {
        size_t r = u - XU;
        int w = (int)(r / WU);
        off = r % WU;
        src = (w == 0) ? wq : (w == 1) ? wk : (w == 2) ? wv : wo;
        H = g_wh + (size_t)w * DD * DD;
        L = g_wl + (size_t)w * DD * DD;
    }
    float4 a = ((const float4*)src)[2 * off];
    float4 b = ((const float4*)src)[2 * off + 1];
    uint4 hv, lv;
    split8(a, b, &hv, &lv);
    ((uint4*)H)[off] = hv;
    ((uint4*)L)[off] = lv;
}

// ===========================================================================
// mma.sync split-bf16 GEMM — EXACT R12 function (non-template, fp32 store).
// grid: (8, 64), 256 threads, 2 CTA/SM.
// ===========================================================================
#define ROWB   80
#define TILE   (128 * ROWB)
#define STAGE  (4 * TILE)
#define GEMM_SMEM (2 * STAGE)

__global__ __launch_bounds__(256) void gemm_mma(const __nv_bfloat16* __restrict__ Ah,
                                                const __nv_bfloat16* __restrict__ Al,
                                                const __nv_bfloat16* __restrict__ Bh,
                                                const __nv_bfloat16* __restrict__ Bl,
                                                float* __restrict__ C) {
    extern __shared__ char smem[];
    const uint32_t sb = smem_u32(smem);
    const int tid  = threadIdx.x;
    const int wid  = tid >> 5;
    const int lane = tid & 31;
    const int wm   = wid & 3;
    const int wn   = wid >> 2;
    const int bn   = blockIdx.x * 128;
    const int bm   = blockIdx.y * 128;

    const char* gAh = (const char*)Ah + (size_t)bm * 2048;
    const char* gAl = (const char*)Al + (size_t)bm * 2048;
    const char* gBh = (const char*)Bh + (size_t)bn * 2048;
    const char* gBl = (const char*)Bl + (size_t)bn * 2048;

    const int tile = tid >> 6;
    const int t6   = tid & 63;
    const char* gsrc = (tile == 0) ? gAh : (tile == 1) ? gAl : (tile == 2) ? gBh : gBl;

    auto issue_copy = [&](int kc, int s) {
        const char* g = gsrc + kc * 64;
        uint32_t dbase = sb + s * STAGE + tile * TILE;
#pragma unroll
        for (int i = 0; i < 8; i++) {
            int unit = t6 + 64 * i;
            int r = unit >> 2, c = unit & 3;
            CP_ASYNC16(dbase + r * ROWB + c * 16, g + (size_t)r * 2048 + c * 16);
        }
        CP_COMMIT();
    };

    float acc[2][8][4];
#pragma unroll
    for (int i = 0; i < 2; i++)
#pragma unroll
        for (int j = 0; j < 8; j++)
#pragma unroll
            for (int e = 0; e < 4; e++) acc[i][j][e] = 0.f;

    const int m8  = (lane >> 3) & 1, k8a = lane >> 4;
    const int n8  = lane >> 4,       k8b = (lane >> 3) & 1;
    const int la7 = lane & 7;

    auto compute = [&](int s) {
        uint32_t aB  = sb + s * STAGE;
        uint32_t alB = aB + TILE;
        uint32_t bB  = aB + 2 * TILE;
        uint32_t blB = aB + 3 * TILE;
#pragma unroll
        for (int s16 = 0; s16 < 2; s16++) {
            int colA = s16 * 32 + k8a * 16;
            int colB = s16 * 32 + k8b * 16;
            uint32_t ah[2][4], al[2][4];
#pragma unroll
            for (int i = 0; i < 2; i++) {
                int row = wm * 32 + i * 16 + m8 * 8 + la7;
                LDSM4(ah[i], aB  + row * ROWB + colA);
                LDSM4(al[i], alB + row * ROWB + colA);
            }
#pragma unroll
            for (int jp = 0; jp < 4; jp++) {
                int row = wn * 64 + jp * 16 + n8 * 8 + la7;
                uint32_t bh[4], bl[4];
                LDSM4(bh, bB  + row * ROWB + colB);
                LDSM4(bl, blB + row * ROWB + colB);
#pragma unroll
                for (int i = 0; i < 2; i++) {
                    MMA16816(acc[i][2 * jp],     ah[i], bh[0], bh[1]);
                    MMA16816(acc[i][2 * jp + 1], ah[i], bh[2], bh[3]);
                    MMA16816(acc[i][2 * jp],     ah[i], bl[0], bl[1]);
                    MMA16816(acc[i][2 * jp + 1], ah[i], bl[2], bl[3]);
                    MMA16816(acc[i][2 * jp],     al[i], bh[0], bh[1]);
                    MMA16816(acc[i][2 * jp + 1], al[i], bh[2], bh[3]);
                }
            }
        }
    };

    issue_copy(0, 0);
    for (int c = 0; c < 32; c++) {
        CP_WAIT0();
        __syncthreads();
        if (c < 31) issue_copy(c + 1, (c + 1) & 1);
        compute(c & 1);
    }

    const int r0 = bm + wm * 32 + (lane >> 2);
    const int c0 = bn + wn * 64 + (lane & 3) * 2;
#pragma unroll
    for (int i = 0; i < 2; i++)
#pragma unroll
        for (int j = 0; j < 8; j++) {
            float* p0 = C + (size_t)(r0 + i * 16) * 1024 + c0 + j * 8;
            float* p1 = C + (size_t)(r0 + i * 16 + 8) * 1024 + c0 + j * 8;
            *(float2*)p0 = make_float2(acc[i][j][0], acc[i][j][1]);
            *(float2*)p1 = make_float2(acc[i][j][2], acc[i][j][3]);
        }
}

// ===========================================================================
// gemm_rope: SEPARATE kernel (same mainloop) whose epilogue applies RoPE via
// the precomputed table and writes bf16 hi/lo. No transcendentals anywhere.
// ===========================================================================
__global__ __launch_bounds__(256) void gemm_rope(const __nv_bfloat16* __restrict__ Ah,
                                                 const __nv_bfloat16* __restrict__ Al,
                                                 const __nv_bfloat16* __restrict__ Bh,
                                                 const __nv_bfloat16* __restrict__ Bl,
                                                 __nv_bfloat16* __restrict__ H,
                                                 __nv_bfloat16* __restrict__ L,
                                                 float scale) {
    extern __shared__ char smem[];
    const uint32_t sb = smem_u32(smem);
    const int tid  = threadIdx.x;
    const int wid  = tid >> 5;
    const int lane = tid & 31;
    const int wm   = wid & 3;
    const int wn   = wid >> 2;
    const int bn   = blockIdx.x * 128;
    const int bm   = blockIdx.y * 128;

    const char* gAh = (const char*)Ah + (size_t)bm * 2048;
    const char* gAl = (const char*)Al + (size_t)bm * 2048;
    const char* gBh = (const char*)Bh + (size_t)bn * 2048;
    const char* gBl = (const char*)Bl + (size_t)bn * 2048;

    const int tile = tid >> 6;
    const int t6   = tid & 63;
    const char* gsrc = (tile == 0) ? gAh : (tile == 1) ? gAl : (tile == 2) ? gBh : gBl;

    auto issue_copy = [&](int kc, int s) {
        const char* g = gsrc + kc * 64;
        uint32_t dbase = sb + s * STAGE + tile * TILE;
#pragma unroll
        for (int i = 0; i < 8; i++) {
            int unit = t6 + 64 * i;
            int r = unit >> 2, c = unit & 3;
            CP_ASYNC16(dbase + r * ROWB + c * 16, g + (size_t)r * 2048 + c * 16);
        }
        CP_COMMIT();
    };

    float acc[2][8][4];
#pragma unroll
    for (int i = 0; i < 2; i++)
#pragma unroll
        for (int j = 0; j < 8; j++)
#pragma unroll
            for (int e = 0; e < 4; e++) acc[i][j][e] = 0.f;

    const int m8  = (lane >> 3) & 1, k8a = lane >> 4;
    const int n8  = lane >> 4,       k8b = (lane >> 3) & 1;
    const int la7 = lane & 7;

    auto compute = [&](int s) {
        uint32_t aB  = sb + s * STAGE;
        uint32_t alB = aB + TILE;
        uint32_t bB  = aB + 2 * TILE;
        uint32_t blB = aB + 3 * TILE;
#pragma unroll
        for (int s16 = 0; s16 < 2; s16++) {
            int colA = s16 * 32 + k8a * 16;
            int colB = s16 * 32 + k8b * 16;
            uint32_t ah[2][4], al[2][4];
#pragma unroll
            for (int i = 0; i < 2; i++) {
                int row = wm * 32 + i * 16 + m8 * 8 + la7;
                LDSM4(ah[i], aB  + row * ROWB + colA);
                LDSM4(al[i], alB + row * ROWB + colA);
            }
#pragma unroll
            for (int jp = 0; jp < 4; jp++) {
                int row = wn * 64 + jp * 16 + n8 * 8 + la7;
                uint32_t bh[4], bl[4];
                LDSM4(bh, bB  + row * ROWB + colB);
                LDSM4(bl, blB + row * ROWB + colB);
#pragma unroll
                for (int i = 0; i < 2; i++) {
                    MMA16816(acc[i][2 * jp],     ah[i], bh[0], bh[1]);
                    MMA16816(acc[i][2 * jp + 1], ah[i], bh[2], bh[3]);
                    MMA16816(acc[i][2 * jp],     ah[i], bl[0], bl[1]);
                    MMA16816(acc[i][2 * jp + 1], ah[i], bl[2], bl[3]);
                    MMA16816(acc[i][2 * jp],     al[i], bh[0], bh[1]);
                    MMA16816(acc[i][2 * jp + 1], al[i], bh[2], bh[3]);
                }
            }
        }
    };

    issue_copy(0, 0);
    for (int c = 0; c < 32; c++) {
        CP_WAIT0();
        __syncthreads();
        if (c < 31) issue_copy(c + 1, (c + 1) & 1);
        compute(c & 1);
    }

    // epilogue: rope rotate (table) + hi/lo split, bf16 stores.
    const int r0 = bm + wm * 32 + (lane >> 2);
    const int c0 = bn + wn * 64 + (lane & 3) * 2;
#pragma unroll
    for (int i = 0; i < 2; i++) {
#pragma unroll
        for (int half = 0; half < 2; half++) {
            int row = r0 + i * 16 + half * 8;
            const float2* trow = g_rope + (size_t)row * 32;
#pragma unroll
            for (int j = 0; j < 8; j++) {
                int col = c0 + 8 * j;
                float2 cs = trow[(col & 63) >> 1];
                float a0 = acc[i][j][2 * half];
                float a1 = acc[i][j][2 * half + 1];
                float ra = (a0 * cs.x - a1 * cs.y) * scale;
                float rb = (a0 * cs.y + a1 * cs.x) * scale;
                uint32_t hh = pack_bf2(ra, rb);
                float2 hb = __bfloat1622float2(*(__nv_bfloat162*)&hh);
                size_t off = (size_t)row * 1024 + col;
                *(uint32_t*)(H + off) = hh;
                *(uint32_t*)(L + off) = pack_bf2(ra - hb.x, rb - hb.y);
            }
        }
    }
}

// ===========================================================================
// vtrans: V split + transpose -> g_vth/g_vtl [b][h][d][T]. grid 2048 x 256.
// ===========================================================================
__global__ __launch_bounds__(256) void vtrans_kernel() {
    __shared__ float vs[64][65];
    const int tid = threadIdx.x;
    const int bh = blockIdx.x >> 5;
    const int b = bh >> 4, h = bh & 15;
    const int t0 = (blockIdx.x & 31) * 64;

#pragma unroll
    for (int i = 0; i < 4; i++) {
        int u = tid + 256 * i;
        int r = u >> 4, c4 = (u & 15) * 4;
        float4 v = *(const float4*)(g_v + (size_t)(b * TT + t0 + r) * DD + h * HD + c4);
        vs[r][c4] = v.x; vs[r][c4 + 1] = v.y; vs[r][c4 + 2] = v.z; vs[r][c4 + 3] = v.w;
    }
    __syncthreads();

#pragma unroll
    for (int i = 0; i < 8; i++) {
        int u = tid + 256 * i;
        int d = u >> 5, tp = u & 31;
        float f0 = vs[2 * tp][d], f1 = vs[2 * tp + 1][d];
        __nv_bfloat162 h2 = __float22bfloat162_rn(make_float2(f0, f1));
        float2 hb = __bfloat1622float2(h2);
        __nv_bfloat162 l2 = __float22bfloat162_rn(make_float2(f0 - hb.x, f1 - hb.y));
        size_t o = ((size_t)(b * 16 + h) * 64 + d) * 2048 + t0 + 2 * tp;
        *(__nv_bfloat162*)(g_vth + o) = h2;
        *(__nv_bfloat162*)(g_vtl + o) = l2;
    }
}

// ===========================================================================
// Tensor-core flash attention (unchanged from R12 best).
// ===========================================================================
#define AROWB 144
#define KTILE_B (64 * AROWB)
#define QTILE_B (128 * AROWB)
#define STG_OFF (2 * QTILE_B)
#define STG_B   (4 * KTILE_B)
#define ATTN2_SMEM (STG_OFF + 2 * STG_B)
#define SM_SHIFT2 14.4269504088896f   // 10 * log2(e)

__global__ __launch_bounds__(256, 2) void attn_mma() {
    extern __shared__ char sm[];
    const uint32_t sb = smem_u32(sm);
    const int tid  = threadIdx.x;
    const int wid  = tid >> 5;
    const int lane = tid & 31;
    const int b = blockIdx.y >> 4, h = blockIdx.y & 15;
    const int q0 = blockIdx.x * 128;

#pragma unroll
    for (int i = 0; i < 8; i++) {
        int u = tid + 256 * i;
        int tens = u >> 10, r = (u >> 3) & 127, c = u & 7;
        const __nv_bfloat16* src = (tens ? g_ql : g_qh)
            + (size_t)(b * TT + q0 + r) * DD + h * HD + c * 8;
        *(uint4*)(sm + tens * QTILE_B + r * AROWB + c * 16) = *(const uint4*)src;
    }

    auto load_stage = [&](int kt, int s) {
        int k0 = kt * 64;
        uint32_t base = sb + STG_OFF + s * STG_B;
#pragma unroll
        for (int i = 0; i < 8; i++) {
            int u = tid + 256 * i;
            int tens = u >> 9, r = (u >> 3) & 63, c = u & 7;
            const __nv_bfloat16* src;
            if (tens == 0)      src = g_kh  + (size_t)(b * TT + k0 + r) * DD + h * HD + c * 8;
            else if (tens == 1) src = g_kl  + (size_t)(b * TT + k0 + r) * DD + h * HD + c * 8;
            else if (tens == 2) src = g_vth + ((size_t)(b * 16 + h) * 64 + r) * 2048 + k0 + c * 8;
            else                src = g_vtl + ((size_t)(b * 16 + h) * 64 + r) * 2048 + k0 + c * 8;
            CP_ASYNC16(base + tens * KTILE_B + r * AROWB + c * 16, src);
        }
        CP_COMMIT();
    };

    const int la7 = lane & 7;
    const int m8  = (lane >> 3) & 1, k8a = lane >> 4;
    const int n8  = lane >> 4,       k8b = (lane >> 3) & 1;

    load_stage(0, 0);

    __syncthreads();
    uint32_t qa[4][4], ql[4][4];
    {
        int arow = wid * 16 + m8 * 8 + la7;
#pragma unroll
        for (int kc = 0; kc < 4; kc++) {
            LDSM4(qa[kc], sb + arow * AROWB + k8a * 16 + kc * 32);
            LDSM4(ql[kc], sb + QTILE_B + arow * AROWB + k8a * 16 + kc * 32);
        }
    }

    float oacc[8][4];
#pragma unroll
    for (int j = 0; j < 8; j++)
#pragma unroll
        for (int e = 0; e < 4; e++) oacc[j][e] = 0.f;
    float rs0 = 0.f, rs1 = 0.f;

    for (int kt = 0; kt < 32; kt++) {
        CP_WAIT0();
        __syncthreads();
        if (kt < 31) load_stage(kt + 1, (kt + 1) & 1);

        uint32_t khB = sb + STG_OFF + (kt & 1) * STG_B;
        uint32_t klB = khB + KTILE_B;
        uint32_t vhB = khB + 2 * KTILE_B;
        uint32_t vlB = khB + 3 * KTILE_B;

        float sacc[8][4];
#pragma unroll
        for (int j = 0; j < 8; j++)
#pragma unroll
            for (int e = 0; e < 4; e++) sacc[j][e] = 0.f;

#pragma unroll
        for (int kc = 0; kc < 4; kc++) {
#pragma unroll
            for (int jp = 0; jp < 4; jp++) {
                int brow = jp * 16 + n8 * 8 + la7;
                uint32_t bh4[4], bl4[4];
                LDSM4(bh4, khB + brow * AROWB + k8b * 16 + kc * 32);
                LDSM4(bl4, klB + brow * AROWB + k8b * 16 + kc * 32);
                MMA16816(sacc[2 * jp],     qa[kc], bh4[0], bh4[1]);
                MMA16816(sacc[2 * jp + 1], qa[kc], bh4[2], bh4[3]);
                MMA16816(sacc[2 * jp],     qa[kc], bl4[0], bl4[1]);
                MMA16816(sacc[2 * jp + 1], qa[kc], bl4[2], bl4[3]);
                MMA16816(sacc[2 * jp],     ql[kc], bh4[0], bh4[1]);
                MMA16816(sacc[2 * jp + 1], ql[kc], bh4[2], bh4[3]);
            }
        }

#pragma unroll
        for (int j = 0; j < 8; j++) {
            sacc[j][0] = fexp2(sacc[j][0] - SM_SHIFT2);
            sacc[j][1] = fexp2(sacc[j][1] - SM_SHIFT2);
            sacc[j][2] = fexp2(sacc[j][2] - SM_SHIFT2);
            sacc[j][3] = fexp2(sacc[j][3] - SM_SHIFT2);
            rs0 += sacc[j][0] + sacc[j][1];
            rs1 += sacc[j][2] + sacc[j][3];
        }

#pragma unroll
        for (int kc = 0; kc < 4; kc++) {
            uint32_t ph[4], pl[4];
#pragma unroll
            for (int t = 0; t < 2; t++) {
                float f0 = sacc[2 * kc + t][0], f1 = sacc[2 * kc + t][1];
                float f2 = sacc[2 * kc + t][2], f3 = sacc[2 * kc + t][3];
                uint32_t h01 = pack_bf2(f0, f1);
                uint32_t h23 = pack_bf2(f2, f3);
                float2 b01 = __bfloat1622float2(*(__nv_bfloat162*)&h01);
                float2 b23 = __bfloat1622float2(*(__nv_bfloat162*)&h23);
                ph[2 * t]     = h01;
                ph[2 * t + 1] = h23;
                pl[2 * t]     = pack_bf2(f0 - b01.x, f1 - b01.y);
                pl[2 * t + 1] = pack_bf2(f2 - b23.x, f3 - b23.y);
            }
#pragma unroll
            for (int dj = 0; dj < 4; dj++) {
                int brow = dj * 16 + n8 * 8 + la7;
                uint32_t vh4[4], vl4[4];
                LDSM4(vh4, vhB + brow * AROWB + k8b * 16 + kc * 32);
                LDSM4(vl4, vlB + brow * AROWB + k8b * 16 + kc * 32);
                MMA16816(oacc[2 * dj],     ph, vh4[0], vh4[1]);
                MMA16816(oacc[2 * dj + 1], ph, vh4[2], vh4[3]);
                MMA16816(oacc[2 * dj],     ph, vl4[0], vl4[1]);
                MMA16816(oacc[2 * dj + 1], ph, vl4[2], vl4[3]);
                MMA16816(oacc[2 * dj],     pl, vh4[0], vh4[1]);
                MMA16816(oacc[2 * dj + 1], pl, vh4[2], vh4[3]);
            }
        }
    }

    rs0 += __shfl_xor_sync(0xffffffffu, rs0, 1);
    rs0 += __shfl_xor_sync(0xffffffffu, rs0, 2);
    rs1 += __shfl_xor_sync(0xffffffffu, rs1, 1);
    rs1 += __shfl_xor_sync(0xffffffffu, rs1, 2);
    float inv0 = 1.0f / rs0, inv1 = 1.0f / rs1;

    int r  = q0 + wid * 16 + (lane >> 2);
    int c0 = h * HD + (lane & 3) * 2;
#pragma unroll
    for (int j = 0; j < 8; j++) {
        float f0 = oacc[j][0] * inv0, f1 = oacc[j][1] * inv0;
        float f2 = oacc[j][2] * inv1, f3 = oacc[j][3] * inv1;
        size_t o0 = (size_t)(b * TT + r) * DD + c0 + 8 * j;
        size_t o1 = (size_t)(b * TT + r + 8) * DD + c0 + 8 * j;
        uint32_t h01 = pack_bf2(f0, f1);
        uint32_t h23 = pack_bf2(f2, f3);
        float2 b01 = __bfloat1622float2(*(__nv_bfloat162*)&h01);
        float2 b23 = __bfloat1622float2(*(__nv_bfloat162*)&h23);
        *(uint32_t*)(g_aoh + o0) = h01;
        *(uint32_t*)(g_aoh + o1) = h23;
        *(uint32_t*)(g_aol + o0) = pack_bf2(f0 - b01.x, f1 - b01.y);
        *(uint32_t*)(g_aol + o1) = pack_bf2(f2 - b23.x, f3 - b23.y);
    }
}

// ---------------------------------------------------------------------------
#define QSCALE 0.1803368801111601f   // 0.125 * log2(e)

extern "C" void kernel_launch(void* const* d_in, const int* in_sizes, int n_in,
                              void* d_out, int out_size) {
    const float* x   = (const float*)d_in[0];
    const float* wq  = (const float*)d_in[1];
    const float* wk  = (const float*)d_in[2];
    const float* wv  = (const float*)d_in[3];
    const float* wo  = (const float*)d_in[4];
    const int*   pos = (const int*)  d_in[5];
    float* out = (float*)d_out;

    __nv_bfloat16 *xh, *xl, *aoh, *aol, *wh, *wl;
    __nv_bfloat16 *qh, *ql, *kh, *kl;
    float *v;
    cudaGetSymbolAddress((void**)&xh,  g_xh);
    cudaGetSymbolAddress((void**)&xl,  g_xl);
    cudaGetSymbolAddress((void**)&aoh, g_aoh);
    cudaGetSymbolAddress((void**)&aol, g_aol);
    cudaGetSymbolAddress((void**)&wh,  g_wh);
    cudaGetSymbolAddress((void**)&wl,  g_wl);
    cudaGetSymbolAddress((void**)&qh,  g_qh);
    cudaGetSymbolAddress((void**)&ql,  g_ql);
    cudaGetSymbolAddress((void**)&kh,  g_kh);
    cudaGetSymbolAddress((void**)&kl,  g_kl);
    cudaGetSymbolAddress((void**)&v,   g_v);

    cudaFuncSetAttribute(gemm_mma,  cudaFuncAttributeMaxDynamicSharedMemorySize, GEMM_SMEM);
    cudaFuncSetAttribute(gemm_rope, cudaFuncAttributeMaxDynamicSharedMemorySize, GEMM_SMEM);
    cudaFuncSetAttribute(attn_mma,  cudaFuncAttributeMaxDynamicSharedMemorySize, ATTN2_SMEM);

    const int NW = DD * DD;
    dim3 ggrid(1024 / 128, MTOT / 128);   // (8, 64), 512 CTAs

    // launch 0: input splits + rope table (tail blocks)
    split_all<<<(SPLIT_UNITS / 256) + TBL_BLOCKS, 256>>>(x, wq, wk, wv, wo, pos);

    // launches 1-2: Q/K projections with fused table-rope + split epilogue
    gemm_rope<<<ggrid, 256, GEMM_SMEM>>>(xh, xl, wh + 0 * NW, wl + 0 * NW, qh, ql, QSCALE);
    gemm_rope<<<ggrid, 256, GEMM_SMEM>>>(xh, xl, wh + 1 * NW, wl + 1 * NW, kh, kl, 1.0f);

    // launch 3: V projection (fp32, exact R12 kernel)
    gemm_mma<<<ggrid, 256, GEMM_SMEM>>>(xh, xl, wh + 2 * NW, wl + 2 * NW, v);

    // launch 4: V split + transpose
    vtrans_kernel<<<TT / 64 * BB * HH, 256>>>();

    // launch 5: tensor-core flash attention (ncu -s 5 lands here)
    attn_mma<<<dim3(TT / 128, BB * HH), 256, ATTN2_SMEM>>>();

    // launch 6: output projection (exact R12 kernel)
    gemm_mma<<<ggrid, 256, GEMM_SMEM>>>(aoh, aol, wh + 3 * NW, wl + 3 * NW, out);
}

// round 15
// speedup vs baseline: 1.6496x; 1.6496x over previous
#include <cuda_runtime.h>
#include <cuda_bf16.h>
#include <math.h>
#include <stdint.h>

#define BB 4
#define TT 2048
#define DD 1024
#define HH 16
#define HD 64
#define MTOT (BB*TT)   // 8192

// ---------------- scratch (device globals: allocation-free) ----------------
__device__ float g_q [MTOT*DD];
__device__ float g_k [MTOT*DD];
__device__ float g_v [MTOT*DD];

__device__ __nv_bfloat16 g_xh [MTOT*DD];
__device__ __nv_bfloat16 g_xl [MTOT*DD];
__device__ __nv_bfloat16 g_aoh[MTOT*DD];
__device__ __nv_bfloat16 g_aol[MTOT*DD];
__device__ __nv_bfloat16 g_wh [4*DD*DD];
__device__ __nv_bfloat16 g_wl [4*DD*DD];

// attention operands (bf16 hi/lo)
__device__ __nv_bfloat16 g_qh [MTOT*DD];
__device__ __nv_bfloat16 g_ql [MTOT*DD];
__device__ __nv_bfloat16 g_kh [MTOT*DD];
__device__ __nv_bfloat16 g_kl [MTOT*DD];
__device__ __nv_bfloat16 g_vth[MTOT*DD];   // [b][h][d][T]
__device__ __nv_bfloat16 g_vtl[MTOT*DD];

// =============================== PTX helpers ===============================
__device__ __forceinline__ uint32_t smem_u32(const void* p) {
    uint32_t a;
    asm("{ .reg .u64 t; cvta.to.shared.u64 t, %1; cvt.u32.u64 %0, t; }" : "=r"(a) : "l"(p));
    return a;
}

#define LDSM4(r, a) \
    asm volatile("ldmatrix.sync.aligned.m8n8.x4.shared.b16 {%0,%1,%2,%3}, [%4];" \
        : "=r"((r)[0]), "=r"((r)[1]), "=r"((r)[2]), "=r"((r)[3]) : "r"(a))

#define MMA16816(d, a, b0, b1) \
    asm volatile("mma.sync.aligned.m16n8k16.row.col.f32.bf16.bf16.f32 " \
        "{%0,%1,%2,%3}, {%4,%5,%6,%7}, {%8,%9}, {%0,%1,%2,%3};" \
        : "+f"((d)[0]), "+f"((d)[1]), "+f"((d)[2]), "+f"((d)[3]) \
        : "r"((a)[0]), "r"((a)[1]), "r"((a)[2]), "r"((a)[3]), "r"(b0), "r"(b1))

#define CP_ASYNC16(dst, src) \
    asm volatile("cp.async.cg.shared.global [%0], [%1], 16;" :: "r"(dst), "l"(src))
#define CP_COMMIT() asm volatile("cp.async.commit_group;" ::: "memory")
#define CP_WAIT0()  asm volatile("cp.async.wait_group 0;" ::: "memory")

// exp2 via magic round + deg-5 poly; input already in log2 domain.
__device__ __forceinline__ float fexp2(float x) {
    x = fmaxf(x, -110.f);
    float zi = x + 12582912.f;          // round-to-nearest integer (magic)
    float fi = zi - 12582912.f;
    float f  = x - fi;                  // f in [-0.5, 0.5]
    int   ei = __float_as_int(zi);      // low bits hold the integer
    float p = 0.00133335581f;
    p = fmaf(p, f, 0.00961812911f);
    p = fmaf(p, f, 0.05550410866f);
    p = fmaf(p, f, 0.24022650700f);
    p = fmaf(p, f, 0.69314718056f);
    p = fmaf(p, f, 1.0f);
    return __int_as_float(__float_as_int(p) + (ei << 23));
}

__device__ __forceinline__ uint32_t pack_bf2(float a, float b) {
    __nv_bfloat162 h = __float22bfloat162_rn(make_float2(a, b));
    return *(uint32_t*)&h;
}

// split 8 floats -> hi/lo uint4
__device__ __forceinline__ void split8(const float4 a, const float4 b,
                                       uint4* H, uint4* L) {
    uint32_t h0 = pack_bf2(a.x, a.y), h1 = pack_bf2(a.z, a.w);
    uint32_t h2 = pack_bf2(b.x, b.y), h3 = pack_bf2(b.z, b.w);
    float2 r0 = __bfloat1622float2(*(__nv_bfloat162*)&h0);
    float2 r1 = __bfloat1622float2(*(__nv_bfloat162*)&h1);
    float2 r2 = __bfloat1622float2(*(__nv_bfloat162*)&h2);
    float2 r3 = __bfloat1622float2(*(__nv_bfloat162*)&h3);
    *H = make_uint4(h0, h1, h2, h3);
    *L = make_uint4(pack_bf2(a.x - r0.x, a.y - r0.y),
                    pack_bf2(a.z - r1.x, a.w - r1.y),
                    pack_bf2(b.x - r2.x, b.y - r2.y),
                    pack_bf2(b.z - r3.x, b.w - r3.y));
}

// ===========================================================================
// split_all: x + 4 weights -> hi/lo bf16 in one launch. grid 6144 x 256.
// ===========================================================================
#define XU (MTOT * DD / 8)
#define WU (DD * DD / 8)

__global__ __launch_bounds__(256) void split_all(const float* __restrict__ x,
                                                 const float* __restrict__ wq,
                                                 const float* __restrict__ wk,
                                                 const float* __restrict__ wv,
                                                 const float* __restrict__ wo) {
    size_t u = (size_t)blockIdx.x * 256 + threadIdx.x;
    const float* src;
    __nv_bfloat16 *H, *L;
    size_t off;
    if (u < XU) {
        src = x; H = g_xh; L = g_xl; off = u;
    } else {
        size_t r = u - XU;
        int w = (int)(r / WU);
        off = r % WU;
        src = (w == 0) ? wq : (w == 1) ? wk : (w == 2) ? wv : wo;
        H = g_wh + (size_t)w * DD * DD;
        L = g_wl + (size_t)w * DD * DD;
    }
    float4 a = ((const float4*)src)[2 * off];
    float4 b = ((const float4*)src)[2 * off + 1];
    uint4 hv, lv;
    split8(a, b, &hv, &lv);
    ((uint4*)H)[off] = hv;
    ((uint4*)L)[off] = lv;
}

// ===========================================================================
// mma.sync split-bf16 GEMM (R6-proven 128x128 tile, separate launches).
// grid: (8, 64), 256 threads, 2 CTA/SM.
// ===========================================================================
#define ROWB   80
#define TILE   (128 * ROWB)
#define STAGE  (4 * TILE)
#define GEMM_SMEM (2 * STAGE)

__global__ __launch_bounds__(256) void gemm_mma(const __nv_bfloat16* __restrict__ Ah,
                                                const __nv_bfloat16* __restrict__ Al,
                                                const __nv_bfloat16* __restrict__ Bh,
                                                const __nv_bfloat16* __restrict__ Bl,
                                                float* __restrict__ C) {
    extern __shared__ char smem[];
    const uint32_t sb = smem_u32(smem);
    const int tid  = threadIdx.x;
    const int wid  = tid >> 5;
    const int lane = tid & 31;
    const int wm   = wid & 3;
    const int wn   = wid >> 2;
    const int bn   = blockIdx.x * 128;
    const int bm   = blockIdx.y * 128;

    const char* gAh = (const char*)Ah + (size_t)bm * 2048;
    const char* gAl = (const char*)Al + (size_t)bm * 2048;
    const char* gBh = (const char*)Bh + (size_t)bn * 2048;
    const char* gBl = (const char*)Bl + (size_t)bn * 2048;

    const int tile = tid >> 6;
    const int t6   = tid & 63;
    const char* gsrc = (tile == 0) ? gAh : (tile == 1) ? gAl : (tile == 2) ? gBh : gBl;

    auto issue_copy = [&](int kc, int s) {
        const char* g = gsrc + kc * 64;
        uint32_t dbase = sb + s * STAGE + tile * TILE;
#pragma unroll
        for (int i = 0; i < 8; i++) {
            int unit = t6 + 64 * i;
            int r = unit >> 2, c = unit & 3;
            CP_ASYNC16(dbase + r * ROWB + c * 16, g + (size_t)r * 2048 + c * 16);
        }
        CP_COMMIT();
    };

    float acc[2][8][4];
#pragma unroll
    for (int i = 0; i < 2; i++)
#pragma unroll
        for (int j = 0; j < 8; j++)
#pragma unroll
            for (int e = 0; e < 4; e++) acc[i][j][e] = 0.f;

    const int m8  = (lane >> 3) & 1, k8a = lane >> 4;
    const int n8  = lane >> 4,       k8b = (lane >> 3) & 1;
    const int la7 = lane & 7;

    auto compute = [&](int s) {
        uint32_t aB  = sb + s * STAGE;
        uint32_t alB = aB + TILE;
        uint32_t bB  = aB + 2 * TILE;
        uint32_t blB = aB + 3 * TILE;
#pragma unroll
        for (int s16 = 0; s16 < 2; s16++) {
            int colA = s16 * 32 + k8a * 16;
            int colB = s16 * 32 + k8b * 16;
            uint32_t ah[2][4], al[2][4];
#pragma unroll
            for (int i = 0; i < 2; i++) {
                int row = wm * 32 + i * 16 + m8 * 8 + la7;
                LDSM4(ah[i], aB  + row * ROWB + colA);
                LDSM4(al[i], alB + row * ROWB + colA);
            }
#pragma unroll
            for (int jp = 0; jp < 4; jp++) {
                int row = wn * 64 + jp * 16 + n8 * 8 + la7;
                uint32_t bh[4], bl[4];
                LDSM4(bh, bB  + row * ROWB + colB);
                LDSM4(bl, blB + row * ROWB + colB);
#pragma unroll
                for (int i = 0; i < 2; i++) {
                    MMA16816(acc[i][2 * jp],     ah[i], bh[0], bh[1]);
                    MMA16816(acc[i][2 * jp + 1], ah[i], bh[2], bh[3]);
                    MMA16816(acc[i][2 * jp],     ah[i], bl[0], bl[1]);
                    MMA16816(acc[i][2 * jp + 1], ah[i], bl[2], bl[3]);
                    MMA16816(acc[i][2 * jp],     al[i], bh[0], bh[1]);
                    MMA16816(acc[i][2 * jp + 1], al[i], bh[2], bh[3]);
                }
            }
        }
    };

    issue_copy(0, 0);
    for (int c = 0; c < 32; c++) {
        CP_WAIT0();
        __syncthreads();
        if (c < 31) issue_copy(c + 1, (c + 1) & 1);
        compute(c & 1);
    }

    const int r0 = bm + wm * 32 + (lane >> 2);
    const int c0 = bn + wn * 64 + (lane & 3) * 2;
#pragma unroll
    for (int i = 0; i < 2; i++)
#pragma unroll
        for (int j = 0; j < 8; j++) {
            float* p0 = C + (size_t)(r0 + i * 16) * 1024 + c0 + j * 8;
            float* p1 = C + (size_t)(r0 + i * 16 + 8) * 1024 + c0 + j * 8;
            *(float2*)p0 = make_float2(acc[i][j][0], acc[i][j][1]);
            *(float2*)p1 = make_float2(acc[i][j][2], acc[i][j][3]);
        }
}

// ===========================================================================
// prep: fused RoPE+split (blocks 0..8191) and V split+transpose (8192..10239)
// Q is scaled by 0.125 * log2(e) so attention scores land in log2 domain.
// ===========================================================================
#define QSCALE 0.1803368801111601f   // 0.125 * log2(e)

__global__ __launch_bounds__(256) void prep_kernel(const int* __restrict__ pos) {
    __shared__ float vs[64][65];
    const int tid = threadIdx.x;

    if (blockIdx.x < MTOT) {
        const int bt = blockIdx.x;
        const float p = (float)pos[bt];
        const float* q = g_q + (size_t)bt * DD;
        const float* k = g_k + (size_t)bt * DD;
        __nv_bfloat162* qh = (__nv_bfloat162*)(g_qh + (size_t)bt * DD);
        __nv_bfloat162* ql = (__nv_bfloat162*)(g_ql + (size_t)bt * DD);
        __nv_bfloat162* kh = (__nv_bfloat162*)(g_kh + (size_t)bt * DD);
        __nv_bfloat162* kl = (__nv_bfloat162*)(g_kl + (size_t)bt * DD);
        const float LN_THETA = 9.210340371976184f;

        for (int pi = tid; pi < DD / 2; pi += 256) {
            int i = pi & 31;
            float inv = __expf(-((float)(2 * i) / 64.0f) * LN_THETA);
            float ang = p * inv;
            float s, c;
            sincosf(ang, &s, &c);
            int idx = 2 * pi;

            float qr = q[idx], qi = q[idx + 1];
            float qa = (qr * c - qi * s) * QSCALE;
            float qb = (qr * s + qi * c) * QSCALE;
            __nv_bfloat162 qh2 = __float22bfloat162_rn(make_float2(qa, qb));
            float2 qhb = __bfloat1622float2(qh2);
            qh[pi] = qh2;
            ql[pi] = __float22bfloat162_rn(make_float2(qa - qhb.x, qb - qhb.y));

            float kr = k[idx], ki = k[idx + 1];
            float ka = kr * c - ki * s;
            float kb = kr * s + ki * c;
            __nv_bfloat162 kh2 = __float22bfloat162_rn(make_float2(ka, kb));
            float2 khb = __bfloat1622float2(kh2);
            kh[pi] = kh2;
            kl[pi] = __float22bfloat162_rn(make_float2(ka - khb.x, kb - khb.y));
        }
    } else {
        const int vblk = blockIdx.x - MTOT;
        const int bh = vblk >> 5;
        const int b = bh >> 4, h = bh & 15;
        const int t0 = (vblk & 31) * 64;

#pragma unroll
        for (int i = 0; i < 4; i++) {
            int u = tid + 256 * i;
            int r = u >> 4, c4 = (u & 15) * 4;
            float4 v = *(const float4*)(g_v + (size_t)(b * TT + t0 + r) * DD + h * HD + c4);
            vs[r][c4] = v.x; vs[r][c4 + 1] = v.y; vs[r][c4 + 2] = v.z; vs[r][c4 + 3] = v.w;
        }
        __syncthreads();

#pragma unroll
        for (int i = 0; i < 8; i++) {
            int u = tid + 256 * i;
            int d = u >> 5, tp = u & 31;
            float f0 = vs[2 * tp][d], f1 = vs[2 * tp + 1][d];
            __nv_bfloat162 h2 = __float22bfloat162_rn(make_float2(f0, f1));
            float2 hb = __bfloat1622float2(h2);
            __nv_bfloat162 l2 = __float22bfloat162_rn(make_float2(f0 - hb.x, f1 - hb.y));
            size_t o = ((size_t)(b * 16 + h) * 64 + d) * 2048 + t0 + 2 * tp;
            *(__nv_bfloat162*)(g_vth + o) = h2;
            *(__nv_bfloat162*)(g_vtl + o) = l2;
        }
    }
}

// ===========================================================================
// Tensor-core flash attention, split-bf16, fixed-shift exp2 softmax.
// Q hi-fragments hoisted to registers (static across all 32 iterations).
// grid: (T/128, B*H), 256 threads, 2 CTA/SM enforced.
// ===========================================================================
#define AROWB 144
#define KTILE_B (64 * AROWB)
#define QTILE_B (128 * AROWB)
#define STG_OFF (2 * QTILE_B)
#define STG_B   (4 * KTILE_B)
#define ATTN2_SMEM (STG_OFF + 2 * STG_B)
#define SM_SHIFT2 14.4269504088896f   // 10 * log2(e)  (scores are log2-domain)

__global__ __launch_bounds__(256, 2) void attn_mma() {
    extern __shared__ char sm[];
    const uint32_t sb = smem_u32(sm);
    const int tid  = threadIdx.x;
    const int wid  = tid >> 5;
    const int lane = tid & 31;
    const int b = blockIdx.y >> 4, h = blockIdx.y & 15;
    const int q0 = blockIdx.x * 128;

#pragma unroll
    for (int i = 0; i < 8; i++) {
        int u = tid + 256 * i;
        int tens = u >> 10, r = (u >> 3) & 127, c = u & 7;
        const __nv_bfloat16* src = (tens ? g_ql : g_qh)
            + (size_t)(b * TT + q0 + r) * DD + h * HD + c * 8;
        *(uint4*)(sm + tens * QTILE_B + r * AROWB + c * 16) = *(const uint4*)src;
    }

    auto load_stage = [&](int kt, int s) {
        int k0 = kt * 64;
        uint32_t base = sb + STG_OFF + s * STG_B;
#pragma unroll
        for (int i = 0; i < 8; i++) {
            int u = tid + 256 * i;
            int tens = u >> 9, r = (u >> 3) & 63, c = u & 7;
            const __nv_bfloat16* src;
            if (tens == 0)      src = g_kh  + (size_t)(b * TT + k0 + r) * DD + h * HD + c * 8;
            else if (tens == 1) src = g_kl  + (size_t)(b * TT + k0 + r) * DD + h * HD + c * 8;
            else if (tens == 2) src = g_vth + ((size_t)(b * 16 + h) * 64 + r) * 2048 + k0 + c * 8;
            else                src = g_vtl + ((size_t)(b * 16 + h) * 64 + r) * 2048 + k0 + c * 8;
            CP_ASYNC16(base + tens * KTILE_B + r * AROWB + c * 16, src);
        }
        CP_COMMIT();
    };

    const int la7 = lane & 7;
    const int m8  = (lane >> 3) & 1, k8a = lane >> 4;
    const int n8  = lane >> 4,       k8b = (lane >> 3) & 1;

    load_stage(0, 0);

    // hoist Q hi fragments into registers (Q tile is static)
    __syncthreads();
    uint32_t qa[4][4];
    {
        int arow = wid * 16 + m8 * 8 + la7;
#pragma unroll
        for (int kc = 0; kc < 4; kc++)
            LDSM4(qa[kc], sb + arow * AROWB + k8a * 16 + kc * 32);
    }

    float oacc[8][4];
#pragma unroll
    for (int j = 0; j < 8; j++)
#pragma unroll
        for (int e = 0; e < 4; e++) oacc[j][e] = 0.f;
    float rs0 = 0.f, rs1 = 0.f;

    for (int kt = 0; kt < 32; kt++) {
        CP_WAIT0();
        __syncthreads();
        if (kt < 31) load_stage(kt + 1, (kt + 1) & 1);

        uint32_t khB = sb + STG_OFF + (kt & 1) * STG_B;
        uint32_t klB = khB + KTILE_B;
        uint32_t vhB = khB + 2 * KTILE_B;
        uint32_t vlB = khB + 3 * KTILE_B;

        float sacc[8][4];
#pragma unroll
        for (int j = 0; j < 8; j++)
#pragma unroll
            for (int e = 0; e < 4; e++) sacc[j][e] = 0.f;

#pragma unroll
        for (int kc = 0; kc < 4; kc++) {
            uint32_t a_l[4];
            int arow = wid * 16 + m8 * 8 + la7;
            LDSM4(a_l, sb + QTILE_B + arow * AROWB + k8a * 16 + kc * 32);
#pragma unroll
            for (int jp = 0; jp < 4; jp++) {
                int brow = jp * 16 + n8 * 8 + la7;
                uint32_t bh4[4], bl4[4];
                LDSM4(bh4, khB + brow * AROWB + k8b * 16 + kc * 32);
                LDSM4(bl4, klB + brow * AROWB + k8b * 16 + kc * 32);
                MMA16816(sacc[2 * jp],     qa[kc], bh4[0], bh4[1]);
                MMA16816(sacc[2 * jp + 1], qa[kc], bh4[2], bh4[3]);
                MMA16816(sacc[2 * jp],     qa[kc], bl4[0], bl4[1]);
                MMA16816(sacc[2 * jp + 1], qa[kc], bl4[2], bl4[3]);
                MMA16816(sacc[2 * jp],     a_l, bh4[0], bh4[1]);
                MMA16816(sacc[2 * jp + 1], a_l, bh4[2], bh4[3]);
            }
        }

#pragma unroll
        for (int j = 0; j < 8; j++) {
            sacc[j][0] = fexp2(sacc[j][0] - SM_SHIFT2);
            sacc[j][1] = fexp2(sacc[j][1] - SM_SHIFT2);
            sacc[j][2] = fexp2(sacc[j][2] - SM_SHIFT2);
            sacc[j][3] = fexp2(sacc[j][3] - SM_SHIFT2);
            rs0 += sacc[j][0] + sacc[j][1];
            rs1 += sacc[j][2] + sacc[j][3];
        }

#pragma unroll
        for (int kc = 0; kc < 4; kc++) {
            uint32_t ph[4], pl[4];
#pragma unroll
            for (int t = 0; t < 2; t++) {
                float f0 = sacc[2 * kc + t][0], f1 = sacc[2 * kc + t][1];
                float f2 = sacc[2 * kc + t][2], f3 = sacc[2 * kc + t][3];
                uint32_t h01 = pack_bf2(f0, f1);
                uint32_t h23 = pack_bf2(f2, f3);
                float2 b01 = __bfloat1622float2(*(__nv_bfloat162*)&h01);
                float2 b23 = __bfloat1622float2(*(__nv_bfloat162*)&h23);
                ph[2 * t]     = h01;
                ph[2 * t + 1] = h23;
                pl[2 * t]     = pack_bf2(f0 - b01.x, f1 - b01.y);
                pl[2 * t + 1] = pack_bf2(f2 - b23.x, f3 - b23.y);
            }
#pragma unroll
            for (int dj = 0; dj < 4; dj++) {
                int brow = dj * 16 + n8 * 8 + la7;
                uint32_t vh4[4], vl4[4];
                LDSM4(vh4, vhB + brow * AROWB + k8b * 16 + kc * 32);
                LDSM4(vl4, vlB + brow * AROWB + k8b * 16 + kc * 32);
                MMA16816(oacc[2 * dj],     ph, vh4[0], vh4[1]);
                MMA16816(oacc[2 * dj + 1], ph, vh4[2], vh4[3]);
                MMA16816(oacc[2 * dj],     ph, vl4[0], vl4[1]);
                MMA16816(oacc[2 * dj + 1], ph, vl4[2], vl4[3]);
                MMA16816(oacc[2 * dj],     pl, vh4[0], vh4[1]);
                MMA16816(oacc[2 * dj + 1], pl, vh4[2], vh4[3]);
            }
        }
    }

    rs0 += __shfl_xor_sync(0xffffffffu, rs0, 1);
    rs0 += __shfl_xor_sync(0xffffffffu, rs0, 2);
    rs1 += __shfl_xor_sync(0xffffffffu, rs1, 1);
    rs1 += __shfl_xor_sync(0xffffffffu, rs1, 2);
    float inv0 = 1.0f / rs0, inv1 = 1.0f / rs1;

    // epilogue: write bf16 hi/lo directly
    int r  = q0 + wid * 16 + (lane >> 2);
    int c0 = h * HD + (lane & 3) * 2;
#pragma unroll
    for (int j = 0; j < 8; j++) {
        float f0 = oacc[j][0] * inv0, f1 = oacc[j][1] * inv0;
        float f2 = oacc[j][2] * inv1, f3 = oacc[j][3] * inv1;
        size_t o0 = (size_t)(b * TT + r) * DD + c0 + 8 * j;
        size_t o1 = (size_t)(b * TT + r + 8) * DD + c0 + 8 * j;
        uint32_t h01 = pack_bf2(f0, f1);
        uint32_t h23 = pack_bf2(f2, f3);
        float2 b01 = __bfloat1622float2(*(__nv_bfloat162*)&h01);
        float2 b23 = __bfloat1622float2(*(__nv_bfloat162*)&h23);
        *(uint32_t*)(g_aoh + o0) = h01;
        *(uint32_t*)(g_aoh + o1) = h23;
        *(uint32_t*)(g_aol + o0) = pack_bf2(f0 - b01.x, f1 - b01.y);
        *(uint32_t*)(g_aol + o1) = pack_bf2(f2 - b23.x, f3 - b23.y);
    }
}

// ---------------------------------------------------------------------------
extern "C" void kernel_launch(void* const* d_in, const int* in_sizes, int n_in,
                              void* d_out, int out_size) {
    const float* x   = (const float*)d_in[0];
    const float* wq  = (const float*)d_in[1];
    const float* wk  = (const float*)d_in[2];
    const float* wv  = (const float*)d_in[3];
    const float* wo  = (const float*)d_in[4];
    const int*   pos = (const int*)  d_in[5];
    float* out = (float*)d_out;

    __nv_bfloat16 *xh, *xl, *aoh, *aol, *wh, *wl;
    float *q, *k, *v;
    cudaGetSymbolAddress((void**)&xh,  g_xh);
    cudaGetSymbolAddress((void**)&xl,  g_xl);
    cudaGetSymbolAddress((void**)&aoh, g_aoh);
    cudaGetSymbolAddress((void**)&aol, g_aol);
    cudaGetSymbolAddress((void**)&wh,  g_wh);
    cudaGetSymbolAddress((void**)&wl,  g_wl);
    cudaGetSymbolAddress((void**)&q,   g_q);
    cudaGetSymbolAddress((void**)&k,   g_k);
    cudaGetSymbolAddress((void**)&v,   g_v);

    cudaFuncSetAttribute(gemm_mma, cudaFuncAttributeMaxDynamicSharedMemorySize, GEMM_SMEM);
    cudaFuncSetAttribute(attn_mma, cudaFuncAttributeMaxDynamicSharedMemorySize, ATTN2_SMEM);

    const int NW = DD * DD;
    dim3 ggrid(1024 / 128, MTOT / 128);   // (8, 64), 512 CTAs

    // launch 0: all input splits fused
    split_all<<<(XU + 4 * WU) / 256, 256>>>(x, wq, wk, wv, wo);

    // launches 1-3: projections (separate launches — R6-measured best)
    gemm_mma<<<ggrid, 256, GEMM_SMEM>>>(xh, xl, wh + 0 * NW, wl + 0 * NW, q);
    gemm_mma<<<ggrid, 256, GEMM_SMEM>>>(xh, xl, wh + 1 * NW, wl + 1 * NW, k);
    gemm_mma<<<ggrid, 256, GEMM_SMEM>>>(xh, xl, wh + 2 * NW, wl + 2 * NW, v);

    // launch 4: rope + V transpose fused
    prep_kernel<<<MTOT + TT / 64 * BB * HH, 256>>>(pos);

    // launch 5: tensor-core flash attention (ncu -s 5 lands here)
    attn_mma<<<dim3(TT / 128, BB * HH), 256, ATTN2_SMEM>>>();

    // launch 6: output projection
    gemm_mma<<<ggrid, 256, GEMM_SMEM>>>(aoh, aol, wh + 3 * NW, wl + 3 * NW, out);
}